// round 4
// baseline (speedup 1.0000x reference)
#include <cuda_runtime.h>

// mean(cumsum(per_sample)) == (1/B) * sum_i per_sample[i] * (B - i)
// => single-pass weighted reduction, no scan needed.

#define WBCE_EPS 1e-10f
#define GRID_MAIN 4144      // 148 SMs * 28
#define THREADS_MAIN 256
#define THREADS_FIN 1024

__device__ double g_partials[GRID_MAIN];

__global__ __launch_bounds__(THREADS_MAIN) void wbce_main_kernel(
    const float* __restrict__ logits,
    const float* __restrict__ targets,
    const float* __restrict__ wp,
    const float* __restrict__ wn,
    long long N4)   // number of float4 groups = B*2 (C=8 -> 2 groups/row)
{
    __shared__ float swp[8];
    __shared__ float swn[8];
    if (threadIdx.x < 8) {
        swp[threadIdx.x] = wp[threadIdx.x];
        swn[threadIdx.x] = wn[threadIdx.x];
    }
    __syncthreads();

    const long long stride = (long long)GRID_MAIN * THREADS_MAIN;   // even
    long long tid = (long long)blockIdx.x * THREADS_MAIN + threadIdx.x;

    // Channel group (0..3 or 4..7) is fixed per thread because stride is even.
    const int cb = ((int)(tid & 1)) * 4;
    const float w0p = swp[cb + 0], w1p = swp[cb + 1], w2p = swp[cb + 2], w3p = swp[cb + 3];
    const float w0n = swn[cb + 0], w1n = swn[cb + 1], w2n = swn[cb + 2], w3n = swn[cb + 3];

    const float4* __restrict__ lg = (const float4*)logits;
    const float4* __restrict__ tg = (const float4*)targets;

    const long long B = N4 >> 1;
    // row(idx) = idx >> 1 advances by stride/2 each iteration (exact, stride even)
    double wrow = (double)(B - (tid >> 1));
    const double wstep = (double)(stride >> 1);

    double acc = 0.0;
    for (long long idx = tid; idx < N4; idx += stride) {
        float4 l = __ldg(lg + idx);
        float4 t = __ldg(tg + idx);

        float s;
        s  = w0p * t.x * __logf(l.x + WBCE_EPS) + w0n * (1.0f - t.x) * __logf(1.0f - l.x + WBCE_EPS);
        s += w1p * t.y * __logf(l.y + WBCE_EPS) + w1n * (1.0f - t.y) * __logf(1.0f - l.y + WBCE_EPS);
        s += w2p * t.z * __logf(l.z + WBCE_EPS) + w2n * (1.0f - t.z) * __logf(1.0f - l.z + WBCE_EPS);
        s += w3p * t.w * __logf(l.w + WBCE_EPS) + w3n * (1.0f - t.w) * __logf(1.0f - l.w + WBCE_EPS);

        // loss is the NEGATED sum; fold negation into the accumulate
        acc -= wrow * (double)s;
        wrow -= wstep;
    }

    // warp reduce (double)
    #pragma unroll
    for (int off = 16; off > 0; off >>= 1)
        acc += __shfl_down_sync(0xffffffffu, acc, off);

    __shared__ double ssum[THREADS_MAIN / 32];
    const int warp = threadIdx.x >> 5;
    if ((threadIdx.x & 31) == 0) ssum[warp] = acc;
    __syncthreads();

    if (threadIdx.x == 0) {
        double b = 0.0;
        #pragma unroll
        for (int w = 0; w < THREADS_MAIN / 32; w++) b += ssum[w];
        g_partials[blockIdx.x] = b;
    }
}

__global__ __launch_bounds__(THREADS_FIN) void wbce_finalize_kernel(float* __restrict__ out,
                                                                    long long B)
{
    double acc = 0.0;
    for (int i = threadIdx.x; i < GRID_MAIN; i += THREADS_FIN)
        acc += g_partials[i];

    #pragma unroll
    for (int off = 16; off > 0; off >>= 1)
        acc += __shfl_down_sync(0xffffffffu, acc, off);

    __shared__ double ssum[THREADS_FIN / 32];
    const int warp = threadIdx.x >> 5;
    if ((threadIdx.x & 31) == 0) ssum[warp] = acc;
    __syncthreads();

    if (threadIdx.x == 0) {
        double tot = 0.0;
        #pragma unroll
        for (int w = 0; w < THREADS_FIN / 32; w++) tot += ssum[w];
        out[0] = (float)(tot / (double)B);
    }
}

extern "C" void kernel_launch(void* const* d_in, const int* in_sizes, int n_in,
                              void* d_out, int out_size) {
    const float* logits  = (const float*)d_in[0];
    const float* targets = (const float*)d_in[1];
    const float* wp      = (const float*)d_in[2];
    const float* wn      = (const float*)d_in[3];

    const long long n_elem = (long long)in_sizes[0];  // B * 8
    const long long N4 = n_elem >> 2;                 // float4 groups
    const long long B  = n_elem >> 3;

    wbce_main_kernel<<<GRID_MAIN, THREADS_MAIN>>>(logits, targets, wp, wn, N4);
    wbce_finalize_kernel<<<1, THREADS_FIN>>>((float*)d_out, B);
}

// round 5
// speedup vs baseline: 1.0231x; 1.0231x over previous
#include <cuda_runtime.h>

// mean(cumsum(per_sample)) == (1/B) * sum_i per_sample[i] * (B - i)
// Single-pass weighted reduction; single kernel with last-block finalize.
//
// Per element, t in {0,1} exactly, so
//   wp*t*log(p+eps) + wn*(1-t)*log(1-p+eps) == (t? wp : wn) * log((t? p : 1-p) + eps)
// (the dead term is w*0*log(finite) == 0 exactly) -> half the MUFU work.

#define WBCE_EPS 1e-10f
#define GRID_MAIN 1184      // 148 SMs * 8
#define THREADS_MAIN 256

__device__ double g_partials[GRID_MAIN];
__device__ unsigned int g_done = 0;   // self-resetting via atomicInc wraparound

__device__ __forceinline__ float elem_term(float l, float t, float wP, float wN) {
    // t is exactly 0.0f or 1.0f
    bool pos = (t != 0.0f);
    float x = pos ? l : (1.0f - l);
    float w = pos ? wP : wN;
    return w * __logf(x + WBCE_EPS);
}

__global__ __launch_bounds__(THREADS_MAIN) void wbce_fused_kernel(
    const float* __restrict__ logits,
    const float* __restrict__ targets,
    const float* __restrict__ wp,
    const float* __restrict__ wn,
    float* __restrict__ out,
    long long N4)   // number of float4 groups = B*2 (C=8 -> 2 groups/row)
{
    __shared__ float swp[8];
    __shared__ float swn[8];
    if (threadIdx.x < 8) {
        swp[threadIdx.x] = wp[threadIdx.x];
        swn[threadIdx.x] = wn[threadIdx.x];
    }
    __syncthreads();

    const long long stride = (long long)GRID_MAIN * THREADS_MAIN;   // even
    const long long tid = (long long)blockIdx.x * THREADS_MAIN + threadIdx.x;

    // Channel half (0..3 or 4..7) is fixed per thread because stride is even.
    const int cb = ((int)(tid & 1)) * 4;
    const float w0p = swp[cb + 0], w1p = swp[cb + 1], w2p = swp[cb + 2], w3p = swp[cb + 3];
    const float w0n = swn[cb + 0], w1n = swn[cb + 1], w2n = swn[cb + 2], w3n = swn[cb + 3];

    const float4* __restrict__ lg = (const float4*)logits;
    const float4* __restrict__ tg = (const float4*)targets;

    const long long B = N4 >> 1;
    // row(idx) = idx >> 1 advances by exactly stride/2 per grid-stride step.
    double wrow = (double)(B - (tid >> 1));
    const double wstep = (double)(stride >> 1);

    double acc = 0.0;
    long long idx = tid;

    // Unrolled x2: 4 independent LDG.128 issued up front (MLP).
    for (; idx + stride < N4; idx += 2 * stride) {
        float4 l0 = __ldg(lg + idx);
        float4 t0 = __ldg(tg + idx);
        float4 l1 = __ldg(lg + idx + stride);
        float4 t1 = __ldg(tg + idx + stride);

        float s0 = elem_term(l0.x, t0.x, w0p, w0n)
                 + elem_term(l0.y, t0.y, w1p, w1n)
                 + elem_term(l0.z, t0.z, w2p, w2n)
                 + elem_term(l0.w, t0.w, w3p, w3n);
        float s1 = elem_term(l1.x, t1.x, w0p, w0n)
                 + elem_term(l1.y, t1.y, w1p, w1n)
                 + elem_term(l1.z, t1.z, w2p, w2n)
                 + elem_term(l1.w, t1.w, w3p, w3n);

        acc -= wrow * (double)s0;
        acc -= (wrow - wstep) * (double)s1;
        wrow -= 2.0 * wstep;
    }
    if (idx < N4) {
        float4 l0 = __ldg(lg + idx);
        float4 t0 = __ldg(tg + idx);
        float s0 = elem_term(l0.x, t0.x, w0p, w0n)
                 + elem_term(l0.y, t0.y, w1p, w1n)
                 + elem_term(l0.z, t0.z, w2p, w2n)
                 + elem_term(l0.w, t0.w, w3p, w3n);
        acc -= wrow * (double)s0;
    }

    // ---- block reduce (double) ----
    #pragma unroll
    for (int off = 16; off > 0; off >>= 1)
        acc += __shfl_down_sync(0xffffffffu, acc, off);

    __shared__ double ssum[THREADS_MAIN / 32];
    const int warp = threadIdx.x >> 5;
    if ((threadIdx.x & 31) == 0) ssum[warp] = acc;
    __syncthreads();

    // ---- last-block finalize ----
    __shared__ bool s_last;
    if (threadIdx.x == 0) {
        double b = 0.0;
        #pragma unroll
        for (int w = 0; w < THREADS_MAIN / 32; w++) b += ssum[w];
        g_partials[blockIdx.x] = b;
        __threadfence();
        // wraps back to 0 when the last block arrives -> graph-replay safe
        unsigned int old = atomicInc(&g_done, GRID_MAIN - 1);
        s_last = (old == GRID_MAIN - 1);
    }
    __syncthreads();

    if (s_last) {
        __threadfence();  // order: observe all partials written before counter
        // Deterministic fixed-order sum regardless of which block is last.
        volatile double* vp = g_partials;
        double a = 0.0;
        for (int i = threadIdx.x; i < GRID_MAIN; i += THREADS_MAIN)
            a += vp[i];

        #pragma unroll
        for (int off = 16; off > 0; off >>= 1)
            a += __shfl_down_sync(0xffffffffu, a, off);

        if ((threadIdx.x & 31) == 0) ssum[warp] = a;
        __syncthreads();

        if (threadIdx.x == 0) {
            double tot = 0.0;
            #pragma unroll
            for (int w = 0; w < THREADS_MAIN / 32; w++) tot += ssum[w];
            out[0] = (float)(tot / (double)B);
        }
    }
}

extern "C" void kernel_launch(void* const* d_in, const int* in_sizes, int n_in,
                              void* d_out, int out_size) {
    const float* logits  = (const float*)d_in[0];
    const float* targets = (const float*)d_in[1];
    const float* wp      = (const float*)d_in[2];
    const float* wn      = (const float*)d_in[3];

    const long long n_elem = (long long)in_sizes[0];  // B * 8
    const long long N4 = n_elem >> 2;                 // float4 groups

    wbce_fused_kernel<<<GRID_MAIN, THREADS_MAIN>>>(logits, targets, wp, wn,
                                                   (float*)d_out, N4);
}

// round 6
// speedup vs baseline: 1.0734x; 1.0492x over previous
#include <cuda_runtime.h>

// mean(cumsum(per_sample)) == (1/B) * sum_i per_sample[i] * (B - i)
// Single-pass weighted reduction; single kernel, last-block finalize.
// GRID = 740 = 148 SMs * 5 blocks (48 regs, 256 thr) -> exactly ONE wave.

#define WBCE_EPS 1e-10f
#define GRID_MAIN 740
#define THREADS_MAIN 256

__device__ double g_partials[GRID_MAIN];
__device__ unsigned int g_done = 0;   // self-resets via atomicInc wraparound

__device__ __forceinline__ float elem_term(float l, float t, float wP, float wN) {
    // t is exactly 0.0f or 1.0f; dead branch contributes exactly 0
    bool pos = (t != 0.0f);
    float x = pos ? l : (1.0f - l);
    float w = pos ? wP : wN;
    return w * __logf(x + WBCE_EPS);
}

__global__ __launch_bounds__(THREADS_MAIN) void wbce_fused_kernel(
    const float* __restrict__ logits,
    const float* __restrict__ targets,
    const float* __restrict__ wp,
    const float* __restrict__ wn,
    float* __restrict__ out,
    long long N4)   // float4 groups = B*2 (C=8 -> 2 groups per row)
{
    __shared__ float swp[8];
    __shared__ float swn[8];
    if (threadIdx.x < 8) {
        swp[threadIdx.x] = wp[threadIdx.x];
        swn[threadIdx.x] = wn[threadIdx.x];
    }
    __syncthreads();

    const long long stride = (long long)GRID_MAIN * THREADS_MAIN;   // even
    const long long tid = (long long)blockIdx.x * THREADS_MAIN + threadIdx.x;

    // Channel half (0..3 or 4..7) fixed per thread (stride even).
    const int cb = ((int)(tid & 1)) * 4;
    const float w0p = swp[cb + 0], w1p = swp[cb + 1], w2p = swp[cb + 2], w3p = swp[cb + 3];
    const float w0n = swn[cb + 0], w1n = swn[cb + 1], w2n = swn[cb + 2], w3n = swn[cb + 3];

    const float4* __restrict__ lg = (const float4*)logits;
    const float4* __restrict__ tg = (const float4*)targets;

    const long long B = N4 >> 1;
    double wrow = (double)(B - (tid >> 1));      // row weight (B - i), exact
    const double wstep = (double)(stride >> 1);  // row advance per grid-stride step

    double acc = 0.0;
    long long idx = tid;

    // Unroll x2: 4 independent LDG.128 in flight per thread.
    for (; idx + stride < N4; idx += 2 * stride) {
        float4 l0 = __ldg(lg + idx);
        float4 t0 = __ldg(tg + idx);
        float4 l1 = __ldg(lg + idx + stride);
        float4 t1 = __ldg(tg + idx + stride);

        float s0 = elem_term(l0.x, t0.x, w0p, w0n)
                 + elem_term(l0.y, t0.y, w1p, w1n)
                 + elem_term(l0.z, t0.z, w2p, w2n)
                 + elem_term(l0.w, t0.w, w3p, w3n);
        float s1 = elem_term(l1.x, t1.x, w0p, w0n)
                 + elem_term(l1.y, t1.y, w1p, w1n)
                 + elem_term(l1.z, t1.z, w2p, w2n)
                 + elem_term(l1.w, t1.w, w3p, w3n);

        // wrow*s0 + (wrow - wstep)*s1 == wrow*(s0+s1) - wstep*s1
        acc -= wrow * (double)(s0 + s1);
        acc += wstep * (double)s1;
        wrow -= 2.0 * wstep;
    }
    if (idx < N4) {
        float4 l0 = __ldg(lg + idx);
        float4 t0 = __ldg(tg + idx);
        float s0 = elem_term(l0.x, t0.x, w0p, w0n)
                 + elem_term(l0.y, t0.y, w1p, w1n)
                 + elem_term(l0.z, t0.z, w2p, w2n)
                 + elem_term(l0.w, t0.w, w3p, w3n);
        acc -= wrow * (double)s0;
    }

    // ---- block reduce (double) ----
    #pragma unroll
    for (int off = 16; off > 0; off >>= 1)
        acc += __shfl_down_sync(0xffffffffu, acc, off);

    __shared__ double ssum[THREADS_MAIN / 32];
    const int warp = threadIdx.x >> 5;
    if ((threadIdx.x & 31) == 0) ssum[warp] = acc;
    __syncthreads();

    // ---- last-block finalize ----
    __shared__ bool s_last;
    if (threadIdx.x == 0) {
        double b = 0.0;
        #pragma unroll
        for (int w = 0; w < THREADS_MAIN / 32; w++) b += ssum[w];
        g_partials[blockIdx.x] = b;
        __threadfence();
        unsigned int old = atomicInc(&g_done, GRID_MAIN - 1);  // wraps to 0
        s_last = (old == GRID_MAIN - 1);
    }
    __syncthreads();

    if (s_last) {
        __threadfence();
        volatile double* vp = g_partials;
        double a = 0.0;
        for (int i = threadIdx.x; i < GRID_MAIN; i += THREADS_MAIN)
            a += vp[i];

        #pragma unroll
        for (int off = 16; off > 0; off >>= 1)
            a += __shfl_down_sync(0xffffffffu, a, off);

        if ((threadIdx.x & 31) == 0) ssum[warp] = a;
        __syncthreads();

        if (threadIdx.x == 0) {
            double tot = 0.0;
            #pragma unroll
            for (int w = 0; w < THREADS_MAIN / 32; w++) tot += ssum[w];
            out[0] = (float)(tot / (double)B);
        }
    }
}

extern "C" void kernel_launch(void* const* d_in, const int* in_sizes, int n_in,
                              void* d_out, int out_size) {
    const float* logits  = (const float*)d_in[0];
    const float* targets = (const float*)d_in[1];
    const float* wp      = (const float*)d_in[2];
    const float* wn      = (const float*)d_in[3];

    const long long n_elem = (long long)in_sizes[0];  // B * 8
    const long long N4 = n_elem >> 2;                 // float4 groups

    wbce_fused_kernel<<<GRID_MAIN, THREADS_MAIN>>>(logits, targets, wp, wn,
                                                   (float*)d_out, N4);
}

// round 7
// speedup vs baseline: 1.0738x; 1.0004x over previous
#include <cuda_runtime.h>

// mean(cumsum(per_sample)) == (1/B) * sum_i per_sample[i] * (B - i)
// Single-pass weighted reduction; single kernel, last-block finalize.
// GRID = 888 = 148 SMs * 6 blocks (<=40 regs via launch_bounds, 256 thr)
// -> exactly ONE wave at 48 warps/SM.
//
// All indices fit int32 (N4 = 2^24). Row weights (B - i) <= 2^23 are exact
// in fp32, so per-pair weighting is done in fp32 and flushed to a double
// accumulator once per pair-iteration (rel err ~5e-7 << 1e-3).

#define WBCE_EPS 1e-10f
#define GRID_MAIN 888
#define THREADS_MAIN 256

__device__ double g_partials[GRID_MAIN];
__device__ unsigned int g_done = 0;   // self-resets via atomicInc wraparound

__device__ __forceinline__ float elem_term(float l, float t, float wP, float wN) {
    // t is exactly 0.0f or 1.0f; dead branch contributes exactly 0
    bool pos = (t != 0.0f);
    float x = pos ? l : (1.0f - l);
    float w = pos ? wP : wN;
    return w * __logf(x + WBCE_EPS);
}

__global__ __launch_bounds__(THREADS_MAIN, 6) void wbce_fused_kernel(
    const float* __restrict__ logits,
    const float* __restrict__ targets,
    const float* __restrict__ wp,
    const float* __restrict__ wn,
    float* __restrict__ out,
    int N4)   // float4 groups = B*2 (C=8 -> 2 groups per row), fits int32
{
    __shared__ float swp[8];
    __shared__ float swn[8];
    if (threadIdx.x < 8) {
        swp[threadIdx.x] = wp[threadIdx.x];
        swn[threadIdx.x] = wn[threadIdx.x];
    }
    __syncthreads();

    const int stride = GRID_MAIN * THREADS_MAIN;           // even
    const int tid = blockIdx.x * THREADS_MAIN + threadIdx.x;

    // Channel half (0..3 or 4..7) fixed per thread (stride even).
    const int cb = (tid & 1) * 4;
    const float w0p = swp[cb + 0], w1p = swp[cb + 1], w2p = swp[cb + 2], w3p = swp[cb + 3];
    const float w0n = swn[cb + 0], w1n = swn[cb + 1], w2n = swn[cb + 2], w3n = swn[cb + 3];

    const float4* __restrict__ lg = (const float4*)logits;
    const float4* __restrict__ tg = (const float4*)targets;

    const int B = N4 >> 1;
    // Row weight (B - i): integer <= 2^23, exact in fp32 throughout.
    float wrow = (float)(B - (tid >> 1));
    const float wstep = (float)(stride >> 1);

    double acc = 0.0;
    int idx = tid;

    // Unroll x2: 4 independent LDG.128 in flight per thread.
    for (; idx + stride < N4; idx += 2 * stride) {
        float4 l0 = __ldg(lg + idx);
        float4 t0 = __ldg(tg + idx);
        float4 l1 = __ldg(lg + idx + stride);
        float4 t1 = __ldg(tg + idx + stride);

        float s0 = elem_term(l0.x, t0.x, w0p, w0n)
                 + elem_term(l0.y, t0.y, w1p, w1n)
                 + elem_term(l0.z, t0.z, w2p, w2n)
                 + elem_term(l0.w, t0.w, w3p, w3n);
        float s1 = elem_term(l1.x, t1.x, w0p, w0n)
                 + elem_term(l1.y, t1.y, w1p, w1n)
                 + elem_term(l1.z, t1.z, w2p, w2n)
                 + elem_term(l1.w, t1.w, w3p, w3n);

        // wrow*s0 + (wrow - wstep)*s1, all fp32; one double add per pair.
        float prod = fmaf(wrow, s0, (wrow - wstep) * s1);
        acc -= (double)prod;
        wrow -= 2.0f * wstep;
    }
    if (idx < N4) {
        float4 l0 = __ldg(lg + idx);
        float4 t0 = __ldg(tg + idx);
        float s0 = elem_term(l0.x, t0.x, w0p, w0n)
                 + elem_term(l0.y, t0.y, w1p, w1n)
                 + elem_term(l0.z, t0.z, w2p, w2n)
                 + elem_term(l0.w, t0.w, w3p, w3n);
        acc -= (double)(wrow * s0);
    }

    // ---- block reduce (double) ----
    #pragma unroll
    for (int off = 16; off > 0; off >>= 1)
        acc += __shfl_down_sync(0xffffffffu, acc, off);

    __shared__ double ssum[THREADS_MAIN / 32];
    const int warp = threadIdx.x >> 5;
    if ((threadIdx.x & 31) == 0) ssum[warp] = acc;
    __syncthreads();

    // ---- last-block finalize ----
    __shared__ bool s_last;
    if (threadIdx.x == 0) {
        double b = 0.0;
        #pragma unroll
        for (int w = 0; w < THREADS_MAIN / 32; w++) b += ssum[w];
        g_partials[blockIdx.x] = b;
        __threadfence();
        unsigned int old = atomicInc(&g_done, GRID_MAIN - 1);  // wraps to 0
        s_last = (old == GRID_MAIN - 1);
    }
    __syncthreads();

    if (s_last) {
        __threadfence();
        volatile double* vp = g_partials;
        double a = 0.0;
        for (int i = threadIdx.x; i < GRID_MAIN; i += THREADS_MAIN)
            a += vp[i];

        #pragma unroll
        for (int off = 16; off > 0; off >>= 1)
            a += __shfl_down_sync(0xffffffffu, a, off);

        if ((threadIdx.x & 31) == 0) ssum[warp] = a;
        __syncthreads();

        if (threadIdx.x == 0) {
            double tot = 0.0;
            #pragma unroll
            for (int w = 0; w < THREADS_MAIN / 32; w++) tot += ssum[w];
            out[0] = (float)(tot / (double)B);
        }
    }
}

extern "C" void kernel_launch(void* const* d_in, const int* in_sizes, int n_in,
                              void* d_out, int out_size) {
    const float* logits  = (const float*)d_in[0];
    const float* targets = (const float*)d_in[1];
    const float* wp      = (const float*)d_in[2];
    const float* wn      = (const float*)d_in[3];

    const int n_elem = in_sizes[0];   // B * 8 = 2^26, fits int32
    const int N4 = n_elem >> 2;       // float4 groups

    wbce_fused_kernel<<<GRID_MAIN, THREADS_MAIN>>>(logits, targets, wp, wn,
                                                   (float*)d_out, N4);
}